// round 5
// baseline (speedup 1.0000x reference)
#include <cuda_runtime.h>
#include <stdint.h>

#define GRID_N 256

__global__ void __launch_bounds__(256) scatter_kernel(
    const float* __restrict__ positions,  // [N,3]
    const float* __restrict__ weights,    // [N]
    float* __restrict__ grid,
    int n_particles)
{
    int t = blockIdx.x * blockDim.x + threadIdx.x;
    if (t >= n_particles) return;

    // XLA rewrites A / dx  ->  A * (1/dx), reciprocal constant-folded in fp32.
    // dx = fp32(20/255); R = fp32(1/dx). Both computed at compile time in IEEE fp32.
    const float dx = 20.0f / 255.0f;
    const float R  = 1.0f / dx;

    float px = __ldg(&positions[3 * t + 0]);
    float py = __ldg(&positions[3 * t + 1]);
    float pz = __ldg(&positions[3 * t + 2]);
    float w  = __ldg(&weights[t]);

    // fi = (p + 10) * R ; then fi + 0.5, trunc toward zero.
    // __fmul_rn/__fadd_rn: forbid FFMA contraction (XLA emits separate mul/add).
    float fx = __fadd_rn(__fmul_rn(__fadd_rn(px, 10.0f), R), 0.5f);
    float fy = __fadd_rn(__fmul_rn(__fadd_rn(py, 10.0f), R), 0.5f);
    float fz = __fadd_rn(__fmul_rn(__fadd_rn(pz, 10.0f), R), 0.5f);

    int ix = (int)fx;   // cvt.rzi: trunc toward zero == astype(int32)
    int iy = (int)fy;
    int iz = (int)fz;

    bool in_grid = (ix >= 0) & (ix < GRID_N) &
                   (iy >= 0) & (iy < GRID_N) &
                   (iz >= 0) & (iz < GRID_N);

    if (in_grid) {
        int flat = (ix * GRID_N + iy) * GRID_N + iz;
        atomicAdd(&grid[flat], w);   // no return use -> REDG, L2-resident
    }
}

extern "C" void kernel_launch(void* const* d_in, const int* in_sizes, int n_in,
                              void* d_out, int out_size)
{
    const float* positions = (const float*)d_in[0];
    const float* weights   = (const float*)d_in[1];
    float* grid            = (float*)d_out;

    int n_particles = in_sizes[1];  // weights has N elements; positions has 3N

    cudaMemsetAsync(grid, 0, (size_t)out_size * sizeof(float), 0);

    int threads = 256;
    int blocks = (n_particles + threads - 1) / threads;
    scatter_kernel<<<blocks, threads>>>(positions, weights, grid, n_particles);
}